// round 16
// baseline (speedup 1.0000x reference)
#include <cuda_runtime.h>

#define NN 128
#define TT 2048
#define DD 88
#define D4 22                   // float4 per row
#define NWORDS (NN * TT / 2)    // 131072 warp-words (1024 per n)
#define STREAM_BLKS (NWORDS / 8)  // 16384
#define WARPS_PER_N 1024ULL

__device__ unsigned int       g_w[NWORDS];        // f0 | f1<<8 | tp<<16 | ti<<26
__device__ unsigned long long g_stat64[NN * 32];  // tp | Ti<<18 | count<<32 (256B stride)
__device__ float              g_acc[NN];
__device__ unsigned int       g_done = 0;

__global__ void __launch_bounds__(256) fused_accuracy(
    const float4* __restrict__ outp,
    const float4* __restrict__ tgtp,
    const int*    __restrict__ mask,
    float*        __restrict__ out)
{
    const int tid  = threadIdx.x;
    const int warp = tid >> 5;
    const int lane = tid & 31;

    if (blockIdx.x < STREAM_BLKS) {
        // ================= stream block: R13 body, warps uncoupled ========
        const int w  = blockIdx.x * 8 + warp;
        const int r0 = w * 2;

        const size_t base = (size_t)r0 * D4 + lane;
        const bool   act  = (lane < D4);

        float4 o0, o1, g0, g1;
        if (act) {
            o0 = __ldcs(outp + base);
            o1 = __ldcs(outp + base + D4);
            g0 = __ldcs(tgtp + base);
            g1 = __ldcs(tgtp + base + D4);
        }
        unsigned int v = 0;
        if (lane == D4)     v = ((unsigned)mask[r0])     << 26;
        if (lane == D4 + 1) v = ((unsigned)mask[r0 + 1]) << 26;

        if (act) {
            int f0 = 0, f1 = 0, tp = 0;
            #define ELEM(ov, gv, fv) {                    \
                const bool p = ((ov) > 0.f);              \
                const bool q = ((gv) != 0.f);             \
                tp += (p && q) ? 1 : 0;                   \
                fv += (p != q) ? 1 : 0; }
            ELEM(o0.x, g0.x, f0) ELEM(o0.y, g0.y, f0) ELEM(o0.z, g0.z, f0) ELEM(o0.w, g0.w, f0)
            ELEM(o1.x, g1.x, f1) ELEM(o1.y, g1.y, f1) ELEM(o1.z, g1.z, f1) ELEM(o1.w, g1.w, f1)
            #undef ELEM
            v = (unsigned)f0 | ((unsigned)f1 << 8) | ((unsigned)tp << 16);
        }

        #pragma unroll
        for (int off = 16; off; off >>= 1)
            v += __shfl_down_sync(0xffffffffu, v, off);

        if (lane == 0) {
            const int n = w >> 10;
            g_w[w] = v;
            __threadfence();      // release g_w before the arrival RED
            const unsigned long long add =
                (unsigned long long)((v >> 16) & 0x3ffu) |
                ((unsigned long long)(v >> 26) << 18) |
                (1ULL << 32);
            atomicAdd(&g_stat64[n << 5], add);
        }
        return;
    }

    // ================= waiter block for sequence n =========================
    const int n = blockIdx.x - STREAM_BLKS;

    __shared__ unsigned long long s_stat;
    __shared__ float s_f[8];
    __shared__ int   s_last;

    if (tid == 0) {
        unsigned long long x;
        do {
            x = *(volatile unsigned long long*)&g_stat64[n << 5];
            if ((x >> 32) != WARPS_PER_N) __nanosleep(128);
        } while ((x >> 32) != WARPS_PER_N);
        s_stat = x;
        g_stat64[n << 5] = 0;     // reset for next graph replay
    }
    __syncthreads();
    __threadfence();              // acquire: order g_w loads after the count

    const float tpf = (float)(s_stat & 0x3ffffu);
    const int   Ti  = (int)((s_stat >> 18) & 0x3fffu);

    const uint4 wv = ((const uint4*)g_w)[n * 256 + tid];   // 4 words = 8 rows
    const int tb = tid * 8;
    float acc = 0.f;
    #define RAT(word, k) {                                                               \
        if (tb + 2*(k)     < Ti) acc += __fdividef(tpf, tpf + (float)( (word)       & 0xffu)); \
        if (tb + 2*(k) + 1 < Ti) acc += __fdividef(tpf, tpf + (float)(((word) >> 8) & 0xffu)); }
    RAT(wv.x, 0) RAT(wv.y, 1) RAT(wv.z, 2) RAT(wv.w, 3)
    #undef RAT

    #pragma unroll
    for (int off = 16; off; off >>= 1)
        acc += __shfl_down_sync(0xffffffffu, acc, off);
    if (lane == 0) s_f[warp] = acc;
    __syncthreads();

    if (tid == 0) {
        float v8 = s_f[0] + s_f[1] + s_f[2] + s_f[3]
                 + s_f[4] + s_f[5] + s_f[6] + s_f[7];
        g_acc[n] = v8 / (float)Ti;
        __threadfence();
        unsigned int old = atomicAdd(&g_done, 1u);
        s_last = (old == NN - 1) ? 1 : 0;
    }
    __syncthreads();
    if (!s_last) return;

    // ---- global finisher: fixed-order 128-way sum ----
    if (warp == 0) {
        __threadfence();
        float vv = g_acc[lane] + g_acc[lane + 32] + g_acc[lane + 64] + g_acc[lane + 96];
        #pragma unroll
        for (int off = 16; off; off >>= 1)
            vv += __shfl_down_sync(0xffffffffu, vv, off);
        if (lane == 0) {
            out[0]  = vv;
            g_done = 0;           // reset for next graph replay
        }
    }
}

extern "C" void kernel_launch(void* const* d_in, const int* in_sizes, int n_in,
                              void* d_out, int out_size)
{
    const float4* outp = (const float4*)d_in[0];
    const float4* tgtp = (const float4*)d_in[1];
    const int*    mask = (const int*)  d_in[2];
    float*        out  = (float*)d_out;

    fused_accuracy<<<STREAM_BLKS + NN, 256>>>(outp, tgtp, mask, out);
}